// round 7
// baseline (speedup 1.0000x reference)
#include <cuda_runtime.h>
#include <cstdint>

#define BATCH    4096
#define NFIELDS  32
#define DIM      64
#define NPAIRS   496
#define BM       32                    // batch rows per tile iteration
#define NITER    (BATCH / BM)          // 128
#define GRID     256                   // one block per pair-group (2 pairs sharing i)
#define NTHREADS 256
#define XSTR     (NFIELDS * DIM)       // 2048
#define OSTR     (NPAIRS * DIM)        // 31744

__device__ __forceinline__ uint32_t f2tf32(float f) {
    uint32_t r;
    asm("cvt.rna.tf32.f32 %0, %1;" : "=r"(r) : "f"(f));
    return r;
}

__device__ __forceinline__ void mma_16x8x8(float* c, uint32_t a0, uint32_t a1,
                                           uint32_t a2, uint32_t a3,
                                           uint32_t b0, uint32_t b1) {
    asm volatile(
        "mma.sync.aligned.m16n8k8.row.col.f32.tf32.tf32.f32 "
        "{%0,%1,%2,%3}, {%4,%5,%6,%7}, {%8,%9}, {%0,%1,%2,%3};"
        : "+f"(c[0]), "+f"(c[1]), "+f"(c[2]), "+f"(c[3])
        : "r"(a0), "r"(a1), "r"(a2), "r"(a3), "r"(b0), "r"(b1));
}

__global__ void __launch_bounds__(NTHREADS, 2)
bilinear_persist_kernel(const float* __restrict__ x,
                        const float* __restrict__ W,
                        float* __restrict__ out) {
    // union region: W tiles [128][68] u32 (8704 words) while loading B regs,
    // then Xi double buffer [2][32][68] (4352 words) for the batch loop.
    __shared__ uint32_t sm[2 * 64 * 68];

    // ---- decode pair-group: pairs (i,j0) and (i,j0+1) ----
    int g = blockIdx.x, fi = 0, p0 = 0, cnt = NFIELDS - 1, gc = 16;
    while (g >= gc) { g -= gc; p0 += cnt; ++fi; cnt = NFIELDS - 1 - fi; gc = (cnt + 1) >> 1; }
    p0 += 2 * g;
    const int j0 = fi + 1 + 2 * g;
    const int npair = (cnt - 2 * g >= 2) ? 2 : 1;

    const int tid  = threadIdx.x;
    const int wid  = tid >> 5, lane = tid & 31;
    const int gq   = lane >> 2, tg = lane & 3;   // quad row / quad lane
    const int u    = wid >> 2;                   // which pair this warp serves
    const int nb   = (wid & 3) * 16;             // 16-col slice within pair

    // ---- stage W[p0..p0+npair) as tf32 into sm[128][68] ----
    #pragma unroll
    for (int t = 0; t < 8; ++t) {
        int idx = tid + t * NTHREADS;
        if (idx < npair * 1024) {
            int uu  = idx >> 10, rem = idx & 1023;
            int row = rem >> 4,  c   = rem & 15;
            float4 v = *reinterpret_cast<const float4*>(
                W + (size_t)(p0 + uu) * (DIM * DIM) + row * DIM + c * 4);
            uint32_t* d = &sm[(uu * 64 + row) * 68 + c * 4];
            d[0] = f2tf32(v.x); d[1] = f2tf32(v.y);
            d[2] = f2tf32(v.z); d[3] = f2tf32(v.w);
        }
    }
    __syncthreads();

    // ---- B fragments -> registers (stationary for the whole batch loop) ----
    // b[kk][nt][r]: B col-major frag for n8-tile nt at k-step kk.
    uint32_t b[8][2][2];
    if (u < npair) {
        #pragma unroll
        for (int kk = 0; kk < 8; ++kk)
            #pragma unroll
            for (int nt = 0; nt < 2; ++nt) {
                int ncol = nb + nt * 8 + gq;     // output col (= W row)
                b[kk][nt][0] = sm[(u * 64 + ncol) * 68 + kk * 8 + tg];
                b[kk][nt][1] = sm[(u * 64 + ncol) * 68 + kk * 8 + tg + 4];
            }
    }
    __syncthreads();   // W region now dead -> becomes Xi double buffer

    // ---- stage Xi for bt = 0 into buffer 0 ----
    {
        #pragma unroll
        for (int t = 0; t < 2; ++t) {
            int idx = tid + t * NTHREADS;       // 512 float4 = 32x64 tile
            int row = idx >> 4, c = idx & 15;
            float4 v = *reinterpret_cast<const float4*>(
                x + (size_t)row * XSTR + fi * DIM + c * 4);
            uint32_t* d = &sm[row * 68 + c * 4];
            d[0] = f2tf32(v.x); d[1] = f2tf32(v.y);
            d[2] = f2tf32(v.z); d[3] = f2tf32(v.w);
        }
    }
    __syncthreads();

    int cur = 0;
    for (int bt = 0; bt < NITER; ++bt) {
        const int bbase = bt * BM;

        // ---- prefetch next Xi tile (overlaps with mma below) ----
        float4 nv0, nv1;
        const bool has_next = (bt + 1 < NITER);
        if (has_next) {
            int nbase = (bt + 1) * BM;
            int i0 = tid, i1 = tid + NTHREADS;
            nv0 = *reinterpret_cast<const float4*>(
                x + (size_t)(nbase + (i0 >> 4)) * XSTR + fi * DIM + (i0 & 15) * 4);
            nv1 = *reinterpret_cast<const float4*>(
                x + (size_t)(nbase + (i1 >> 4)) * XSTR + fi * DIM + (i1 & 15) * 4);
        }

        // ---- GEMM: warp computes 32 rows x 16 cols of proj for pair u ----
        float acc[2][2][4] = {};
        if (u < npair) {
            const uint32_t* sx = sm + cur * (32 * 68);
            #pragma unroll
            for (int kk = 0; kk < 8; ++kk) {
                const int k0 = kk * 8;
                #pragma unroll
                for (int mt = 0; mt < 2; ++mt) {
                    const int r = mt * 16 + gq;
                    uint32_t a0 = sx[ r      * 68 + k0 + tg    ];
                    uint32_t a1 = sx[(r + 8) * 68 + k0 + tg    ];
                    uint32_t a2 = sx[ r      * 68 + k0 + tg + 4];
                    uint32_t a3 = sx[(r + 8) * 68 + k0 + tg + 4];
                    mma_16x8x8(acc[mt][0], a0, a1, a2, a3, b[kk][0][0], b[kk][0][1]);
                    mma_16x8x8(acc[mt][1], a0, a1, a2, a3, b[kk][1][0], b[kk][1][1]);
                }
            }
        }

        // ---- store prefetched tile into the other buffer ----
        if (has_next) {
            uint32_t* d = sm + (cur ^ 1) * (32 * 68);
            int i0 = tid, i1 = tid + NTHREADS;
            uint32_t* d0 = d + (i0 >> 4) * 68 + (i0 & 15) * 4;
            d0[0] = f2tf32(nv0.x); d0[1] = f2tf32(nv0.y);
            d0[2] = f2tf32(nv0.z); d0[3] = f2tf32(nv0.w);
            uint32_t* d1 = d + (i1 >> 4) * 68 + (i1 & 15) * 4;
            d1[0] = f2tf32(nv1.x); d1[1] = f2tf32(nv1.y);
            d1[2] = f2tf32(nv1.z); d1[3] = f2tf32(nv1.w);
        }

        // ---- epilogue: out[b,p,:] = proj * x[b,j,:] ----
        if (u < npair) {
            const int p = p0 + u, j = j0 + u;
            #pragma unroll
            for (int mt = 0; mt < 2; ++mt) {
                const int r0 = bbase + mt * 16 + gq;
                const int r1 = r0 + 8;
                #pragma unroll
                for (int nt = 0; nt < 2; ++nt) {
                    const int col = nb + nt * 8 + tg * 2;
                    float2 xj0 = *reinterpret_cast<const float2*>(
                        x + (size_t)r0 * XSTR + j * DIM + col);
                    float2 xj1 = *reinterpret_cast<const float2*>(
                        x + (size_t)r1 * XSTR + j * DIM + col);
                    *reinterpret_cast<float2*>(
                        out + (size_t)r0 * OSTR + p * DIM + col) =
                        make_float2(acc[mt][nt][0] * xj0.x, acc[mt][nt][1] * xj0.y);
                    *reinterpret_cast<float2*>(
                        out + (size_t)r1 * OSTR + p * DIM + col) =
                        make_float2(acc[mt][nt][2] * xj1.x, acc[mt][nt][3] * xj1.y);
                }
            }
        }
        __syncthreads();
        cur ^= 1;
    }
}

extern "C" void kernel_launch(void* const* d_in, const int* in_sizes, int n_in,
                              void* d_out, int out_size) {
    const float* x = (const float*)d_in[0];
    const float* W = (const float*)d_in[1];
    float* out = (float*)d_out;
    bilinear_persist_kernel<<<GRID, NTHREADS>>>(x, W, out);
}

// round 8
// speedup vs baseline: 1.1847x; 1.1847x over previous
#include <cuda_runtime.h>
#include <cstdint>

#define BATCH    4096
#define NFIELDS  32
#define DIM      64
#define NPAIRS   496
#define BM       32                    // batch rows per iteration
#define NSPLIT   8                     // batch splits per pair-group
#define ROWS_PB  (BATCH / NSPLIT)      // 512 rows per block
#define NITER    (ROWS_PB / BM)        // 16
#define NGROUPS  256
#define GRID     (NGROUPS * NSPLIT)    // 2048
#define NTHREADS 256
#define XSTR     (NFIELDS * DIM)       // 2048
#define OSTR     (NPAIRS * DIM)        // 31744
#define SO_STR   132                   // sOut row stride (words)
#define SO_BASE  (BM * 68)             // 2176 words: sOut after sXi

__device__ __forceinline__ uint32_t f2tf32(float f) {
    uint32_t r;
    asm("cvt.rna.tf32.f32 %0, %1;" : "=r"(r) : "f"(f));
    return r;
}

__device__ __forceinline__ void mma_16x8x8(float* c, uint32_t a0, uint32_t a1,
                                           uint32_t a2, uint32_t a3,
                                           uint32_t b0, uint32_t b1) {
    asm volatile(
        "mma.sync.aligned.m16n8k8.row.col.f32.tf32.tf32.f32 "
        "{%0,%1,%2,%3}, {%4,%5,%6,%7}, {%8,%9}, {%0,%1,%2,%3};"
        : "+f"(c[0]), "+f"(c[1]), "+f"(c[2]), "+f"(c[3])
        : "r"(a0), "r"(a1), "r"(a2), "r"(a3), "r"(b0), "r"(b1));
}

__global__ void __launch_bounds__(NTHREADS, 3)
bilinear_split_kernel(const float* __restrict__ x,
                      const float* __restrict__ W,
                      float* __restrict__ out) {
    // union: W-staging phase uses [2*64*68] words; loop uses sXi[32*68] + sOut[32*132]
    __shared__ uint32_t sm[2 * 64 * 68];   // 34816 B

    // ---- decode block -> (pair-group, batch split) ----
    int g = blockIdx.x >> 3;
    const int sbase = (blockIdx.x & 7) * ROWS_PB;
    int fi = 0, p0 = 0, cnt = NFIELDS - 1, gc = 16;
    while (g >= gc) { g -= gc; p0 += cnt; ++fi; cnt = NFIELDS - 1 - fi; gc = (cnt + 1) >> 1; }
    p0 += 2 * g;
    const int j0 = fi + 1 + 2 * g;
    const int npair = (cnt - 2 * g >= 2) ? 2 : 1;

    const int tid  = threadIdx.x;
    const int wid  = tid >> 5, lane = tid & 31;
    const int gq   = lane >> 2, tg = lane & 3;
    const int u    = wid >> 2;                 // pair served by this warp
    const int nb   = (wid & 3) * 16;           // 16-col slice

    // ---- stage W tiles, pull B fragments into registers (once) ----
    #pragma unroll
    for (int t = 0; t < 8; ++t) {
        int idx = tid + t * NTHREADS;
        if (idx < npair * 1024) {
            int uu = idx >> 10, rem = idx & 1023;
            int row = rem >> 4, c = rem & 15;
            float4 v = *reinterpret_cast<const float4*>(
                W + (size_t)(p0 + uu) * (DIM * DIM) + row * DIM + c * 4);
            uint32_t* d = &sm[(uu * 64 + row) * 68 + c * 4];
            d[0] = f2tf32(v.x); d[1] = f2tf32(v.y);
            d[2] = f2tf32(v.z); d[3] = f2tf32(v.w);
        }
    }
    __syncthreads();

    uint32_t b[8][2][2];
    if (u < npair) {
        #pragma unroll
        for (int kk = 0; kk < 8; ++kk)
            #pragma unroll
            for (int nt = 0; nt < 2; ++nt) {
                int ncol = nb + nt * 8 + gq;
                b[kk][nt][0] = sm[(u * 64 + ncol) * 68 + kk * 8 + tg];
                b[kk][nt][1] = sm[(u * 64 + ncol) * 68 + kk * 8 + tg + 4];
            }
    }
    __syncthreads();

    for (int bt = 0; bt < NITER; ++bt) {
        const int bbase = sbase + bt * BM;

        // ---- stage Xi [32 x 64] as tf32 ----
        #pragma unroll
        for (int t = 0; t < 2; ++t) {
            int idx = tid + t * NTHREADS;      // 512 float4
            int row = idx >> 4, c = idx & 15;
            float4 v = *reinterpret_cast<const float4*>(
                x + (size_t)(bbase + row) * XSTR + fi * DIM + c * 4);
            uint32_t* d = &sm[row * 68 + c * 4];
            d[0] = f2tf32(v.x); d[1] = f2tf32(v.y);
            d[2] = f2tf32(v.z); d[3] = f2tf32(v.w);
        }
        __syncthreads();

        // ---- GEMM: 32 rows x 16 cols per warp ----
        float acc[2][2][4] = {};
        if (u < npair) {
            #pragma unroll
            for (int kk = 0; kk < 8; ++kk) {
                const int k0 = kk * 8;
                #pragma unroll
                for (int mt = 0; mt < 2; ++mt) {
                    const int r = mt * 16 + gq;
                    uint32_t a0 = sm[ r      * 68 + k0 + tg    ];
                    uint32_t a1 = sm[(r + 8) * 68 + k0 + tg    ];
                    uint32_t a2 = sm[ r      * 68 + k0 + tg + 4];
                    uint32_t a3 = sm[(r + 8) * 68 + k0 + tg + 4];
                    mma_16x8x8(acc[mt][0], a0, a1, a2, a3, b[kk][0][0], b[kk][0][1]);
                    mma_16x8x8(acc[mt][1], a0, a1, a2, a3, b[kk][1][0], b[kk][1][1]);
                }
            }
            // ---- acc -> sOut (row-major, stride 132) ----
            #pragma unroll
            for (int mt = 0; mt < 2; ++mt)
                #pragma unroll
                for (int nt = 0; nt < 2; ++nt) {
                    const int col = u * 64 + nb + nt * 8 + tg * 2;
                    uint32_t* s0 = &sm[SO_BASE + (mt * 16 + gq    ) * SO_STR + col];
                    uint32_t* s1 = &sm[SO_BASE + (mt * 16 + gq + 8) * SO_STR + col];
                    s0[0] = __float_as_uint(acc[mt][nt][0]);
                    s0[1] = __float_as_uint(acc[mt][nt][1]);
                    s1[0] = __float_as_uint(acc[mt][nt][2]);
                    s1[1] = __float_as_uint(acc[mt][nt][3]);
                }
        }

        // ---- issue xj loads before the barrier (overlap latency) ----
        float4 xj[4];
        if (npair == 2) {
            #pragma unroll
            for (int t = 0; t < 4; ++t) {
                int idx = tid + t * NTHREADS;  // 1024 float4
                int row = idx >> 5, cc = idx & 31;
                int uu = cc >> 4, c = cc & 15;
                xj[t] = *reinterpret_cast<const float4*>(
                    x + (size_t)(bbase + row) * XSTR + (j0 + uu) * DIM + c * 4);
            }
        } else {
            #pragma unroll
            for (int t = 0; t < 2; ++t) {
                int idx = tid + t * NTHREADS;  // 512 float4
                int row = idx >> 4, c = idx & 15;
                xj[t] = *reinterpret_cast<const float4*>(
                    x + (size_t)(bbase + row) * XSTR + j0 * DIM + c * 4);
            }
        }
        __syncthreads();

        // ---- coalesced final pass: out = proj * xj ----
        if (npair == 2) {
            #pragma unroll
            for (int t = 0; t < 4; ++t) {
                int idx = tid + t * NTHREADS;
                int row = idx >> 5, cc = idx & 31;
                int uu = cc >> 4, c = cc & 15;
                const float* so = reinterpret_cast<const float*>(
                    &sm[SO_BASE + row * SO_STR + uu * 64 + c * 4]);
                float4 o = make_float4(so[0] * xj[t].x, so[1] * xj[t].y,
                                       so[2] * xj[t].z, so[3] * xj[t].w);
                *reinterpret_cast<float4*>(
                    out + (size_t)(bbase + row) * OSTR + (size_t)(p0 + uu) * DIM + c * 4) = o;
            }
        } else {
            #pragma unroll
            for (int t = 0; t < 2; ++t) {
                int idx = tid + t * NTHREADS;
                int row = idx >> 4, c = idx & 15;
                const float* so = reinterpret_cast<const float*>(
                    &sm[SO_BASE + row * SO_STR + c * 4]);
                float4 o = make_float4(so[0] * xj[t].x, so[1] * xj[t].y,
                                       so[2] * xj[t].z, so[3] * xj[t].w);
                *reinterpret_cast<float4*>(
                    out + (size_t)(bbase + row) * OSTR + (size_t)p0 * DIM + c * 4) = o;
            }
        }
        __syncthreads();   // sXi/sOut reuse hazard for next iteration
    }
}

extern "C" void kernel_launch(void* const* d_in, const int* in_sizes, int n_in,
                              void* d_out, int out_size) {
    const float* x = (const float*)d_in[0];
    const float* W = (const float*)d_in[1];
    float* out = (float*)d_out;
    bilinear_split_kernel<<<GRID, NTHREADS>>>(x, W, out);
}

// round 11
// speedup vs baseline: 1.3796x; 1.1645x over previous
#include <cuda_runtime.h>
#include <cuda_fp16.h>
#include <cstdint>

#define BATCH    4096
#define NFIELDS  32
#define DIM      64
#define NPAIRS   496
#define BM       32                    // batch rows per iteration
#define NSPLIT   8                     // batch splits per pair-group
#define ROWS_PB  (BATCH / NSPLIT)      // 512
#define NITER    (ROWS_PB / BM)        // 16
#define NGROUPS  256
#define GRID     (NGROUPS * NSPLIT)    // 2048
#define NTHREADS 256
#define XSTR     (NFIELDS * DIM)       // 2048
#define OSTR     (NPAIRS * DIM)        // 31744

// smem (words): sXi [32][36] half2-words, sOut [32][132] f32. W staged at base.
#define XI_STR   36
#define SO_STR   132
#define SO_BASE  (BM * XI_STR)         // 1152
#define SM_WORDS (SO_BASE + BM * SO_STR)   // 5376 words = 21504 B

__device__ __forceinline__ uint32_t pack_h2(float lo, float hi) {
    __half2 h = __floats2half2_rn(lo, hi);
    return *reinterpret_cast<uint32_t*>(&h);
}

__device__ __forceinline__ void mma_16x8x16(float* c, uint32_t a0, uint32_t a1,
                                            uint32_t a2, uint32_t a3,
                                            uint32_t b0, uint32_t b1) {
    asm volatile(
        "mma.sync.aligned.m16n8k16.row.col.f32.f16.f16.f32 "
        "{%0,%1,%2,%3}, {%4,%5,%6,%7}, {%8,%9}, {%0,%1,%2,%3};"
        : "+f"(c[0]), "+f"(c[1]), "+f"(c[2]), "+f"(c[3])
        : "r"(a0), "r"(a1), "r"(a2), "r"(a3), "r"(b0), "r"(b1));
}

__global__ void __launch_bounds__(NTHREADS, 4)
bilinear_f16_kernel(const float* __restrict__ x,
                    const float* __restrict__ W,
                    float* __restrict__ out) {
    __shared__ uint32_t sm[SM_WORDS];

    // ---- decode block -> (pair-group, batch split) ----
    int g = blockIdx.x >> 3;
    const int sbase = (blockIdx.x & 7) * ROWS_PB;
    int fi = 0, p0 = 0, cnt = NFIELDS - 1, gc = 16;
    while (g >= gc) { g -= gc; p0 += cnt; ++fi; cnt = NFIELDS - 1 - fi; gc = (cnt + 1) >> 1; }
    p0 += 2 * g;
    const int j0 = fi + 1 + 2 * g;
    const int npair = (cnt - 2 * g >= 2) ? 2 : 1;

    const int tid  = threadIdx.x;
    const int wid  = tid >> 5, lane = tid & 31;
    const int gq   = lane >> 2, tg = lane & 3;
    const int u    = wid >> 2;                 // pair served by this warp
    const int nb   = (wid & 3) * 16;           // 16-col slice

    // ---- stage W tiles as half2 words [npair*64][36] ----
    #pragma unroll
    for (int t = 0; t < 8; ++t) {
        int idx = tid + t * NTHREADS;
        if (idx < npair * 1024) {
            int uu = idx >> 10, rem = idx & 1023;
            int row = rem >> 4, c = rem & 15;
            float4 v = *reinterpret_cast<const float4*>(
                W + (size_t)(p0 + uu) * (DIM * DIM) + row * DIM + c * 4);
            uint32_t* d = &sm[(uu * 64 + row) * XI_STR + c * 2];
            d[0] = pack_h2(v.x, v.y);
            d[1] = pack_h2(v.z, v.w);
        }
    }
    __syncthreads();

    // ---- B fragments -> registers (stationary) ----
    // b[kk][nt][r]: for mma k-step kk (k = 16*kk), n8-tile nt.
    uint32_t b[4][2][2];
    if (u < npair) {
        #pragma unroll
        for (int kk = 0; kk < 4; ++kk)
            #pragma unroll
            for (int nt = 0; nt < 2; ++nt) {
                int ncol = nb + nt * 8 + gq;   // output col = W row
                b[kk][nt][0] = sm[(u * 64 + ncol) * XI_STR + kk * 8 + tg];
                b[kk][nt][1] = sm[(u * 64 + ncol) * XI_STR + kk * 8 + tg + 4];
            }
    }
    __syncthreads();

    for (int bt = 0; bt < NITER; ++bt) {
        const int bbase = sbase + bt * BM;

        // ---- stage Xi [32 x 64] as half2 words ----
        #pragma unroll
        for (int t = 0; t < 2; ++t) {
            int idx = tid + t * NTHREADS;      // 512 float4
            int row = idx >> 4, c = idx & 15;
            float4 v = *reinterpret_cast<const float4*>(
                x + (size_t)(bbase + row) * XSTR + fi * DIM + c * 4);
            uint32_t* d = &sm[row * XI_STR + c * 2];
            d[0] = pack_h2(v.x, v.y);
            d[1] = pack_h2(v.z, v.w);
        }
        __syncthreads();

        // ---- GEMM: 32 rows x 16 cols per warp, K=64 in 4 steps ----
        float acc[2][2][4] = {};
        if (u < npair) {
            #pragma unroll
            for (int kk = 0; kk < 4; ++kk) {
                const int k0 = kk * 8;
                #pragma unroll
                for (int mt = 0; mt < 2; ++mt) {
                    const int r = mt * 16 + gq;
                    uint32_t a0 = sm[ r      * XI_STR + k0 + tg    ];
                    uint32_t a1 = sm[(r + 8) * XI_STR + k0 + tg    ];
                    uint32_t a2 = sm[ r      * XI_STR + k0 + tg + 4];
                    uint32_t a3 = sm[(r + 8) * XI_STR + k0 + tg + 4];
                    mma_16x8x16(acc[mt][0], a0, a1, a2, a3, b[kk][0][0], b[kk][0][1]);
                    mma_16x8x16(acc[mt][1], a0, a1, a2, a3, b[kk][1][0], b[kk][1][1]);
                }
            }
            // ---- acc -> sOut ----
            #pragma unroll
            for (int mt = 0; mt < 2; ++mt)
                #pragma unroll
                for (int nt = 0; nt < 2; ++nt) {
                    const int col = u * 64 + nb + nt * 8 + tg * 2;
                    uint32_t* s0 = &sm[SO_BASE + (mt * 16 + gq    ) * SO_STR + col];
                    uint32_t* s1 = &sm[SO_BASE + (mt * 16 + gq + 8) * SO_STR + col];
                    s0[0] = __float_as_uint(acc[mt][nt][0]);
                    s0[1] = __float_as_uint(acc[mt][nt][1]);
                    s1[0] = __float_as_uint(acc[mt][nt][2]);
                    s1[1] = __float_as_uint(acc[mt][nt][3]);
                }
        }

        // ---- xj loads before barrier (latency overlap) ----
        float4 xj[4];
        if (npair == 2) {
            #pragma unroll
            for (int t = 0; t < 4; ++t) {
                int idx = tid + t * NTHREADS;  // 1024 float4
                int row = idx >> 5, cc = idx & 31;
                int uu = cc >> 4, c = cc & 15;
                xj[t] = *reinterpret_cast<const float4*>(
                    x + (size_t)(bbase + row) * XSTR + (j0 + uu) * DIM + c * 4);
            }
        } else {
            #pragma unroll
            for (int t = 0; t < 2; ++t) {
                int idx = tid + t * NTHREADS;  // 512 float4
                int row = idx >> 4, c = idx & 15;
                xj[t] = *reinterpret_cast<const float4*>(
                    x + (size_t)(bbase + row) * XSTR + j0 * DIM + c * 4);
            }
        }
        __syncthreads();

        // ---- coalesced final pass: out = proj * xj ----
        if (npair == 2) {
            #pragma unroll
            for (int t = 0; t < 4; ++t) {
                int idx = tid + t * NTHREADS;
                int row = idx >> 5, cc = idx & 31;
                int uu = cc >> 4, c = cc & 15;
                const float* so = reinterpret_cast<const float*>(
                    &sm[SO_BASE + row * SO_STR + uu * 64 + c * 4]);
                float4 o = make_float4(so[0] * xj[t].x, so[1] * xj[t].y,
                                       so[2] * xj[t].z, so[3] * xj[t].w);
                *reinterpret_cast<float4*>(
                    out + (size_t)(bbase + row) * OSTR + (size_t)(p0 + uu) * DIM + c * 4) = o;
            }
        } else {
            #pragma unroll
            for (int t = 0; t < 2; ++t) {
                int idx = tid + t * NTHREADS;
                int row = idx >> 4, c = idx & 15;
                const float* so = reinterpret_cast<const float*>(
                    &sm[SO_BASE + row * SO_STR + c * 4]);
                float4 o = make_float4(so[0] * xj[t].x, so[1] * xj[t].y,
                                       so[2] * xj[t].z, so[3] * xj[t].w);
                *reinterpret_cast<float4*>(
                    out + (size_t)(bbase + row) * OSTR + (size_t)p0 * DIM + c * 4) = o;
            }
        }
        __syncthreads();   // protect sXi/sOut reuse next iteration
    }
}

extern "C" void kernel_launch(void* const* d_in, const int* in_sizes, int n_in,
                              void* d_out, int out_size) {
    const float* x = (const float*)d_in[0];
    const float* W = (const float*)d_in[1];
    float* out = (float*)d_out;
    bilinear_f16_kernel<<<GRID, NTHREADS>>>(x, W, out);
}

// round 12
// speedup vs baseline: 1.3910x; 1.0083x over previous
#include <cuda_runtime.h>
#include <cuda_fp16.h>
#include <cstdint>

#define BATCH    4096
#define NFIELDS  32
#define DIM      64
#define NPAIRS   496
#define BM       32                    // batch rows per iteration
#define NSPLIT   8                     // batch splits per pair-group
#define ROWS_PB  (BATCH / NSPLIT)      // 512
#define NITER    (ROWS_PB / BM)        // 16
#define NGROUPS  256
#define GRID     (NGROUPS * NSPLIT)    // 2048
#define NTHREADS 256
#define XSTR     (NFIELDS * DIM)       // 2048
#define OSTR     (NPAIRS * DIM)        // 31744

// smem (words): sXi [32][36] half2-words, sOut [32][132] f32. W staged at base.
#define XI_STR   36
#define SO_STR   132
#define SO_BASE  (BM * XI_STR)         // 1152
#define SM_WORDS (SO_BASE + BM * SO_STR)   // 5376 words = 21504 B

__device__ __forceinline__ uint32_t pack_h2(float lo, float hi) {
    __half2 h = __floats2half2_rn(lo, hi);
    return *reinterpret_cast<uint32_t*>(&h);
}

__device__ __forceinline__ void mma_16x8x16(float* c, uint32_t a0, uint32_t a1,
                                            uint32_t a2, uint32_t a3,
                                            uint32_t b0, uint32_t b1) {
    asm volatile(
        "mma.sync.aligned.m16n8k16.row.col.f32.f16.f16.f32 "
        "{%0,%1,%2,%3}, {%4,%5,%6,%7}, {%8,%9}, {%0,%1,%2,%3};"
        : "+f"(c[0]), "+f"(c[1]), "+f"(c[2]), "+f"(c[3])
        : "r"(a0), "r"(a1), "r"(a2), "r"(a3), "r"(b0), "r"(b1));
}

__global__ void __launch_bounds__(NTHREADS, 4)
bilinear_f16_kernel(const float* __restrict__ x,
                    const float* __restrict__ W,
                    float* __restrict__ out) {
    __shared__ uint32_t sm[SM_WORDS];

    // ---- decode block -> (pair-group, batch split) ----
    int g = blockIdx.x >> 3;
    const int sbase = (blockIdx.x & 7) * ROWS_PB;
    int fi = 0, p0 = 0, cnt = NFIELDS - 1, gc = 16;
    while (g >= gc) { g -= gc; p0 += cnt; ++fi; cnt = NFIELDS - 1 - fi; gc = (cnt + 1) >> 1; }
    p0 += 2 * g;
    const int j0 = fi + 1 + 2 * g;
    const int npair = (cnt - 2 * g >= 2) ? 2 : 1;

    const int tid  = threadIdx.x;
    const int wid  = tid >> 5, lane = tid & 31;
    const int gq   = lane >> 2, tg = lane & 3;
    const int u    = wid >> 2;                 // pair served by this warp
    const int nb   = (wid & 3) * 16;           // 16-col slice

    // ---- stage W tiles as half2 words [npair*64][36] ----
    #pragma unroll
    for (int t = 0; t < 8; ++t) {
        int idx = tid + t * NTHREADS;
        if (idx < npair * 1024) {
            int uu = idx >> 10, rem = idx & 1023;
            int row = rem >> 4, c = rem & 15;
            float4 v = *reinterpret_cast<const float4*>(
                W + (size_t)(p0 + uu) * (DIM * DIM) + row * DIM + c * 4);
            uint32_t* d = &sm[(uu * 64 + row) * XI_STR + c * 2];
            d[0] = pack_h2(v.x, v.y);
            d[1] = pack_h2(v.z, v.w);
        }
    }
    __syncthreads();

    // ---- B fragments -> registers (stationary) ----
    // b[kk][nt][r]: for mma k-step kk (k = 16*kk), n8-tile nt.
    uint32_t b[4][2][2];
    if (u < npair) {
        #pragma unroll
        for (int kk = 0; kk < 4; ++kk)
            #pragma unroll
            for (int nt = 0; nt < 2; ++nt) {
                int ncol = nb + nt * 8 + gq;   // output col = W row
                b[kk][nt][0] = sm[(u * 64 + ncol) * XI_STR + kk * 8 + tg];
                b[kk][nt][1] = sm[(u * 64 + ncol) * XI_STR + kk * 8 + tg + 4];
            }
    }
    __syncthreads();

    for (int bt = 0; bt < NITER; ++bt) {
        const int bbase = sbase + bt * BM;

        // ---- stage Xi [32 x 64] as half2 words ----
        #pragma unroll
        for (int t = 0; t < 2; ++t) {
            int idx = tid + t * NTHREADS;      // 512 float4
            int row = idx >> 4, c = idx & 15;
            float4 v = *reinterpret_cast<const float4*>(
                x + (size_t)(bbase + row) * XSTR + fi * DIM + c * 4);
            uint32_t* d = &sm[row * XI_STR + c * 2];
            d[0] = pack_h2(v.x, v.y);
            d[1] = pack_h2(v.z, v.w);
        }
        __syncthreads();

        // ---- GEMM: 32 rows x 16 cols per warp, K=64 in 4 steps ----
        float acc[2][2][4] = {};
        if (u < npair) {
            #pragma unroll
            for (int kk = 0; kk < 4; ++kk) {
                const int k0 = kk * 8;
                #pragma unroll
                for (int mt = 0; mt < 2; ++mt) {
                    const int r = mt * 16 + gq;
                    uint32_t a0 = sm[ r      * XI_STR + k0 + tg    ];
                    uint32_t a1 = sm[(r + 8) * XI_STR + k0 + tg    ];
                    uint32_t a2 = sm[ r      * XI_STR + k0 + tg + 4];
                    uint32_t a3 = sm[(r + 8) * XI_STR + k0 + tg + 4];
                    mma_16x8x16(acc[mt][0], a0, a1, a2, a3, b[kk][0][0], b[kk][0][1]);
                    mma_16x8x16(acc[mt][1], a0, a1, a2, a3, b[kk][1][0], b[kk][1][1]);
                }
            }
            // ---- acc -> sOut ----
            #pragma unroll
            for (int mt = 0; mt < 2; ++mt)
                #pragma unroll
                for (int nt = 0; nt < 2; ++nt) {
                    const int col = u * 64 + nb + nt * 8 + tg * 2;
                    uint32_t* s0 = &sm[SO_BASE + (mt * 16 + gq    ) * SO_STR + col];
                    uint32_t* s1 = &sm[SO_BASE + (mt * 16 + gq + 8) * SO_STR + col];
                    s0[0] = __float_as_uint(acc[mt][nt][0]);
                    s0[1] = __float_as_uint(acc[mt][nt][1]);
                    s1[0] = __float_as_uint(acc[mt][nt][2]);
                    s1[1] = __float_as_uint(acc[mt][nt][3]);
                }
        }

        // ---- xj loads before barrier (latency overlap) ----
        float4 xj[4];
        if (npair == 2) {
            #pragma unroll
            for (int t = 0; t < 4; ++t) {
                int idx = tid + t * NTHREADS;  // 1024 float4
                int row = idx >> 5, cc = idx & 31;
                int uu = cc >> 4, c = cc & 15;
                xj[t] = *reinterpret_cast<const float4*>(
                    x + (size_t)(bbase + row) * XSTR + (j0 + uu) * DIM + c * 4);
            }
        } else {
            #pragma unroll
            for (int t = 0; t < 2; ++t) {
                int idx = tid + t * NTHREADS;  // 512 float4
                int row = idx >> 4, c = idx & 15;
                xj[t] = *reinterpret_cast<const float4*>(
                    x + (size_t)(bbase + row) * XSTR + j0 * DIM + c * 4);
            }
        }
        __syncthreads();

        // ---- coalesced final pass: out = proj * xj ----
        if (npair == 2) {
            #pragma unroll
            for (int t = 0; t < 4; ++t) {
                int idx = tid + t * NTHREADS;
                int row = idx >> 5, cc = idx & 31;
                int uu = cc >> 4, c = cc & 15;
                const float* so = reinterpret_cast<const float*>(
                    &sm[SO_BASE + row * SO_STR + uu * 64 + c * 4]);
                float4 o = make_float4(so[0] * xj[t].x, so[1] * xj[t].y,
                                       so[2] * xj[t].z, so[3] * xj[t].w);
                *reinterpret_cast<float4*>(
                    out + (size_t)(bbase + row) * OSTR + (size_t)(p0 + uu) * DIM + c * 4) = o;
            }
        } else {
            #pragma unroll
            for (int t = 0; t < 2; ++t) {
                int idx = tid + t * NTHREADS;
                int row = idx >> 4, c = idx & 15;
                const float* so = reinterpret_cast<const float*>(
                    &sm[SO_BASE + row * SO_STR + c * 4]);
                float4 o = make_float4(so[0] * xj[t].x, so[1] * xj[t].y,
                                       so[2] * xj[t].z, so[3] * xj[t].w);
                *reinterpret_cast<float4*>(
                    out + (size_t)(bbase + row) * OSTR + (size_t)p0 * DIM + c * 4) = o;
            }
        }
        __syncthreads();   // protect sXi/sOut reuse next iteration
    }
}

extern "C" void kernel_launch(void* const* d_in, const int* in_sizes, int n_in,
                              void* d_out, int out_size) {
    const float* x = (const float*)d_in[0];
    const float* W = (const float*)d_in[1];
    float* out = (float*)d_out;
    bilinear_f16_kernel<<<GRID, NTHREADS>>>(x, W, out);
}